// round 14
// baseline (speedup 1.0000x reference)
#include <cuda_runtime.h>
#include <cuda_bf16.h>
#include <cuda_fp16.h>
#include <stdint.h>

#define NND 50000
#define EMAX 320000
#define HDIM 128

// ---------------- scratch (device globals; allocation-free contract) --------
__device__ int            g_deg[NND];
__device__ float          g_dinv[NND];
__device__ __half         g_h[(size_t)NND * HDIM];     // fp16 message buffer
__device__ __half         g_z[(size_t)NND * HDIM];     // final z (fp16)
__device__ __nv_bfloat16  g_ah[(size_t)NND * HDIM];
__device__ __nv_bfloat16  g_al[(size_t)NND * HDIM];
// W0 at [0, 32768), W1 at [32768, 49152), W2 at [49152, 65536)
__device__ __nv_bfloat16  g_wh[65536];
__device__ __nv_bfloat16  g_wl[65536];
// CSR
__device__ int g_off[NND + 1];
__device__ int g_cur[NND];
__device__ int g_csr[EMAX];
__device__ int g_part[256];
// grid barrier counters (monotone across launches; generation = ctr/count)
__device__ unsigned g_barrier[16];

// ---------------- grid barrier (persistent-kernel, generation counting) -----
__device__ __forceinline__ void gbar(int slot, unsigned count) {
    __threadfence();
    __syncthreads();
    if (threadIdx.x == 0) {
        unsigned old = atomicAdd(&g_barrier[slot], 1u);
        unsigned target = old - (old % count) + count;
        while (*(volatile unsigned*)&g_barrier[slot] < target) __nanosleep(64);
        __threadfence();
    }
    __syncthreads();
}

// ---------------- bf16 split helper ----------------
__device__ __forceinline__ void split_store4(float4 v, __nv_bfloat16* ah,
                                             __nv_bfloat16* al, size_t off) {
    float hx = __bfloat162float(__float2bfloat16(v.x));
    float hy = __bfloat162float(__float2bfloat16(v.y));
    float hz = __bfloat162float(__float2bfloat16(v.z));
    float hw = __bfloat162float(__float2bfloat16(v.w));
    __nv_bfloat162 h01 = __floats2bfloat162_rn(hx, hy);
    __nv_bfloat162 h23 = __floats2bfloat162_rn(hz, hw);
    __nv_bfloat162 l01 = __floats2bfloat162_rn(v.x - hx, v.y - hy);
    __nv_bfloat162 l23 = __floats2bfloat162_rn(v.z - hz, v.w - hw);
    uint2 hp, lp;
    hp.x = *(uint32_t*)&h01; hp.y = *(uint32_t*)&h23;
    lp.x = *(uint32_t*)&l01; lp.y = *(uint32_t*)&l23;
    *(uint2*)&ah[off] = hp;
    *(uint2*)&al[off] = lp;
}

// ---------------- HMMA GEMM phase: H(fp16) = A @ W^T (bf16x3 split) ----------
#define MMA16816(d, a, b) \
    asm volatile( \
        "mma.sync.aligned.m16n8k16.row.col.f32.bf16.bf16.f32 " \
        "{%0,%1,%2,%3}, {%4,%5,%6,%7}, {%8,%9}, {%0,%1,%2,%3};" \
        : "+f"((d)[0]), "+f"((d)[1]), "+f"((d)[2]), "+f"((d)[3]) \
        : "r"((a)[0]), "r"((a)[1]), "r"((a)[2]), "r"((a)[3]), \
          "r"((b)[0]), "r"((b)[1]))

template <int K, bool FUSE>
__device__ __forceinline__ void gemm_phase(
    const __nv_bfloat16* __restrict__ Ah, const __nv_bfloat16* __restrict__ Al,
    const float* __restrict__ Xf,
    const __nv_bfloat16* __restrict__ Wh, const __nv_bfloat16* __restrict__ Wl,
    __half* __restrict__ H, int M, int cta, int ncta, char* smem)
{
    const int PW = K + 8;   // W row pitch (bf16)
    const int PA = 24;      // A row pitch (bf16)
    __nv_bfloat16* sWh = (__nv_bfloat16*)smem;
    __nv_bfloat16* sWl = sWh + 128 * PW;
    __nv_bfloat16* sA  = sWl + 128 * PW;   // [stage][buf][128][PA]

    const int tid = threadIdx.x, lane = tid & 31, wid = tid >> 5;
    const int wm = wid & 3, wn = wid >> 2;

    // load W (hi+lo) once per layer
    const int WCH = 128 * (K / 8);
    for (int i = tid; i < WCH; i += 256) {
        int n = i / (K / 8), c = i % (K / 8);
        *(uint4*)(sWh + n * PW + c * 8) = __ldcg((const uint4*)(Wh + n * K + c * 8));
        *(uint4*)(sWl + n * PW + c * 8) = __ldcg((const uint4*)(Wl + n * K + c * 8));
    }
    __syncthreads();

    const int ntiles = (M + 127) / 128;
    for (int tile = cta; tile < ntiles; tile += ncta) {
        const int m0 = tile * 128;

        auto copyA = [&](int ks, int st) {
            if (FUSE) {
                int row = tid >> 1, half = tid & 1;
                int gr = m0 + row;
                float4 v0 = make_float4(0.f, 0.f, 0.f, 0.f), v1 = v0;
                if (gr < M) {
                    const float4* p = (const float4*)(Xf + (size_t)gr * K + ks * 16 + half * 8);
                    v0 = p[0]; v1 = p[1];
                }
                float f[8] = {v0.x, v0.y, v0.z, v0.w, v1.x, v1.y, v1.z, v1.w};
                uint32_t hi[4], lo[4];
#pragma unroll
                for (int j = 0; j < 4; j++) {
                    float a = f[2 * j], b = f[2 * j + 1];
                    float ha = __bfloat162float(__float2bfloat16(a));
                    float hb = __bfloat162float(__float2bfloat16(b));
                    __nv_bfloat162 hh = __floats2bfloat162_rn(ha, hb);
                    __nv_bfloat162 ll = __floats2bfloat162_rn(a - ha, b - hb);
                    hi[j] = *(uint32_t*)&hh;
                    lo[j] = *(uint32_t*)&ll;
                }
                __nv_bfloat16* dh = sA + ((st * 2 + 0) * 128 + row) * PA + half * 8;
                __nv_bfloat16* dl = sA + ((st * 2 + 1) * 128 + row) * PA + half * 8;
                *(uint4*)dh = make_uint4(hi[0], hi[1], hi[2], hi[3]);
                *(uint4*)dl = make_uint4(lo[0], lo[1], lo[2], lo[3]);
            } else {
                int buf = tid >> 7, row = tid & 127;
                int gr = m0 + row;
                const __nv_bfloat16* src = buf ? Al : Ah;
                uint4 v0 = make_uint4(0u, 0u, 0u, 0u), v1 = v0;
                if (gr < M) {
                    const uint4* p = (const uint4*)(src + (size_t)gr * K + ks * 16);
                    v0 = __ldcg(p); v1 = __ldcg(p + 1);   // bypass L1 (rewritten between layers)
                }
                __nv_bfloat16* d = sA + ((st * 2 + buf) * 128 + row) * PA;
                *(uint4*)d = v0; *(uint4*)(d + 8) = v1;
            }
        };

        float acc[2][8][4];
#pragma unroll
        for (int mt = 0; mt < 2; mt++)
#pragma unroll
            for (int nt = 0; nt < 8; nt++)
#pragma unroll
                for (int j = 0; j < 4; j++) acc[mt][nt][j] = 0.f;

        const int NS = K / 16;
        copyA(0, 0);
        __syncthreads();

        const int ar0 = wm * 32 + (lane >> 2);
        const int kk  = (lane & 3) * 2;
        const int nb  = wn * 64 + (lane >> 2);

        for (int ks = 0; ks < NS; ks++) {
            int st = ks & 1;
            if (ks + 1 < NS) copyA(ks + 1, st ^ 1);

            const __nv_bfloat16* Abh = sA + (st * 2 + 0) * 128 * PA;
            const __nv_bfloat16* Abl = sA + (st * 2 + 1) * 128 * PA;

            uint32_t ah[2][4], al[2][4];
#pragma unroll
            for (int mt = 0; mt < 2; mt++) {
                int r = ar0 + mt * 16;
                ah[mt][0] = *(const uint32_t*)(Abh + r * PA + kk);
                ah[mt][1] = *(const uint32_t*)(Abh + (r + 8) * PA + kk);
                ah[mt][2] = *(const uint32_t*)(Abh + r * PA + kk + 8);
                ah[mt][3] = *(const uint32_t*)(Abh + (r + 8) * PA + kk + 8);
                al[mt][0] = *(const uint32_t*)(Abl + r * PA + kk);
                al[mt][1] = *(const uint32_t*)(Abl + (r + 8) * PA + kk);
                al[mt][2] = *(const uint32_t*)(Abl + r * PA + kk + 8);
                al[mt][3] = *(const uint32_t*)(Abl + (r + 8) * PA + kk + 8);
            }
            uint32_t bh[8][2], bl[8][2];
            int kw = ks * 16 + kk;
#pragma unroll
            for (int nt = 0; nt < 8; nt++) {
                const __nv_bfloat16* ph = sWh + (nb + nt * 8) * PW + kw;
                const __nv_bfloat16* pl = sWl + (nb + nt * 8) * PW + kw;
                bh[nt][0] = *(const uint32_t*)ph;
                bh[nt][1] = *(const uint32_t*)(ph + 8);
                bl[nt][0] = *(const uint32_t*)pl;
                bl[nt][1] = *(const uint32_t*)(pl + 8);
            }
#pragma unroll
            for (int mt = 0; mt < 2; mt++)
#pragma unroll
                for (int nt = 0; nt < 8; nt++) {
                    MMA16816(acc[mt][nt], ah[mt], bh[nt]);  // hi*hi
                    MMA16816(acc[mt][nt], ah[mt], bl[nt]);  // hi*lo
                    MMA16816(acc[mt][nt], al[mt], bh[nt]);  // lo*hi
                }
            __syncthreads();
        }

        // epilogue: write raw H as fp16
        const int cbase = wn * 64 + (lane & 3) * 2;
#pragma unroll
        for (int mt = 0; mt < 2; mt++) {
            int ra = m0 + wm * 32 + mt * 16 + (lane >> 2);
            int rb = ra + 8;
#pragma unroll
            for (int nt = 0; nt < 8; nt++) {
                int col = cbase + nt * 8;
                if (ra < M)
                    *(__half2*)&H[(size_t)ra * HDIM + col] =
                        __floats2half2_rn(acc[mt][nt][0], acc[mt][nt][1]);
                if (rb < M)
                    *(__half2*)&H[(size_t)rb * HDIM + col] =
                        __floats2half2_rn(acc[mt][nt][2], acc[mt][nt][3]);
            }
        }
        __syncthreads();
    }
}

// ---------------- fused aggregate + finalize phase ---------------------------
__device__ __forceinline__ void acc_row(float4& acc, uint2 rv, float ds) {
    float2 v01 = __half22float2(*(__half2*)&rv.x);
    float2 v23 = __half22float2(*(__half2*)&rv.y);
    acc.x = fmaf(v01.x, ds, acc.x); acc.y = fmaf(v01.y, ds, acc.y);
    acc.z = fmaf(v23.x, ds, acc.z); acc.w = fmaf(v23.y, ds, acc.w);
}
template <bool BF16OUT>
__device__ __forceinline__ void agg_phase(
    const __half* __restrict__ H, const float* __restrict__ bias,
    __half* __restrict__ OUT, int N, int gw0, int gstep)
{
    int lane = threadIdx.x & 31;
    for (int gw = gw0; gw < N; gw += gstep) {
        int s0 = __ldcg(&g_off[gw]), s1 = __ldcg(&g_off[gw + 1]);
        float di = __ldcg(&g_dinv[gw]);
        uint2 raw = __ldcg((const uint2*)&H[(size_t)gw * HDIM + lane * 4]);  // self
        float2 p01 = __half22float2(*(__half2*)&raw.x);
        float2 p23 = __half22float2(*(__half2*)&raw.y);
        float4 acc = make_float4(p01.x * di, p01.y * di, p23.x * di, p23.y * di);

        int j = s0;
        for (; j + 4 <= s1; j += 4) {
            int sa = __ldcg(&g_csr[j]),     sb = __ldcg(&g_csr[j + 1]);
            int sc = __ldcg(&g_csr[j + 2]), sd = __ldcg(&g_csr[j + 3]);
            float da = __ldcg(&g_dinv[sa]), db = __ldcg(&g_dinv[sb]);
            float dc = __ldcg(&g_dinv[sc]), dd = __ldcg(&g_dinv[sd]);
            uint2 ra = __ldcg((const uint2*)&H[(size_t)sa * HDIM + lane * 4]);
            uint2 rb = __ldcg((const uint2*)&H[(size_t)sb * HDIM + lane * 4]);
            uint2 rc = __ldcg((const uint2*)&H[(size_t)sc * HDIM + lane * 4]);
            uint2 rd = __ldcg((const uint2*)&H[(size_t)sd * HDIM + lane * 4]);
            acc_row(acc, ra, da); acc_row(acc, rb, db);
            acc_row(acc, rc, dc); acc_row(acc, rd, dd);
        }
        for (; j < s1; j++) {
            int s = __ldcg(&g_csr[j]);
            float ds = __ldcg(&g_dinv[s]);
            uint2 rv = __ldcg((const uint2*)&H[(size_t)s * HDIM + lane * 4]);
            acc_row(acc, rv, ds);
        }

        float4 bb = *(const float4*)&bias[lane * 4];
        acc.x = acc.x * di + bb.x; acc.y = acc.y * di + bb.y;
        acc.z = acc.z * di + bb.z; acc.w = acc.w * di + bb.w;
        if (BF16OUT) {
            acc.x = fmaxf(acc.x, 0.f); acc.y = fmaxf(acc.y, 0.f);
            acc.z = fmaxf(acc.z, 0.f); acc.w = fmaxf(acc.w, 0.f);
            split_store4(acc, g_ah, g_al, (size_t)gw * HDIM + lane * 4);
        } else {
            uint2 o;
            *(__half2*)&o.x = __floats2half2_rn(acc.x, acc.y);
            *(__half2*)&o.y = __floats2half2_rn(acc.z, acc.w);
            *(uint2*)&OUT[(size_t)gw * HDIM + lane * 4] = o;
        }
    }
}

// ---------------- decode phase ------------------------------------------------
__device__ __forceinline__ void decode_phase(
    const __half* __restrict__ Z, const int* __restrict__ ea,
    const int* __restrict__ eb, float* __restrict__ out, int EL,
    int gw0, int gstep)
{
    int lane = threadIdx.x & 31;
    for (int gw = gw0; gw < EL; gw += gstep) {
        int i = ea[gw], j = eb[gw];
        uint2 ru = __ldcg((const uint2*)&Z[(size_t)i * HDIM + lane * 4]);
        uint2 rv = __ldcg((const uint2*)&Z[(size_t)j * HDIM + lane * 4]);
        float2 u01 = __half22float2(*(__half2*)&ru.x);
        float2 u23 = __half22float2(*(__half2*)&ru.y);
        float2 v01 = __half22float2(*(__half2*)&rv.x);
        float2 v23 = __half22float2(*(__half2*)&rv.y);
        float p = u01.x * v01.x + u01.y * v01.y + u23.x * v23.x + u23.y * v23.y;
#pragma unroll
        for (int o = 16; o; o >>= 1) p += __shfl_xor_sync(0xffffffffu, p, o);
        if (lane == 0) out[gw] = p;
    }
}

// ---------------- the persistent mega-kernel ----------------------------------
__global__ __launch_bounds__(256, 1) void mega_kernel(
    const float* __restrict__ x,
    const int* __restrict__ src, const int* __restrict__ dst,
    const int* __restrict__ la, const int* __restrict__ lb,
    const float* __restrict__ W0, const float* __restrict__ b0,
    const float* __restrict__ W1, const float* __restrict__ b1,
    const float* __restrict__ W2, const float* __restrict__ b2,
    float* __restrict__ logits,
    int N, int E, int EL, int ncta)
{
    extern __shared__ char smem[];
    const int cta = blockIdx.x, tid = threadIdx.x;
    const unsigned csr_n = (unsigned)(ncta - 128);
    const int nblk = (N + 255) / 256;

    if (cta < 128) {
        // ---- main branch: W split, then layer-0 GEMM (dinv-free) ----
        for (int j = cta * 256 + tid; j < 65536; j += 128 * 256) {
            const float* W; int K2, jj = j;
            if (j < 32768)      { W = W0; K2 = 256; }
            else if (j < 49152) { W = W1; K2 = 128; jj -= 32768; }
            else                { W = W2; K2 = 128; jj -= 49152; }
            int nn = jj / K2, k = jj % K2;
            float v = W[k * 128 + nn];
            float h = __bfloat162float(__float2bfloat16(v));
            g_wh[j] = __float2bfloat16(h);
            g_wl[j] = __float2bfloat16(v - h);
        }
        gbar(0, 128u);
        gemm_phase<256, true>(nullptr, nullptr, x, g_wh, g_wl, g_h, N, cta, 128, smem);
    } else {
        // ---- side branch: degrees + CSR + dinv (runs concurrently with GEMM0)
        int ccta = cta - 128;
        for (int i = ccta * 256 + tid; i < N; i += (int)csr_n * 256) g_deg[i] = 1;
        gbar(1, csr_n);
        for (int e = ccta * 256 + tid; e < E; e += (int)csr_n * 256)
            atomicAdd(&g_deg[dst[e]], 1);
        gbar(2, csr_n);
        int* sh = (int*)smem;
        for (int b = ccta; b < nblk; b += (int)csr_n) {
            int i = b * 256 + tid;
            int v = (i < N) ? __ldcg(&g_deg[i]) - 1 : 0;
            sh[tid] = v;
            __syncthreads();
#pragma unroll
            for (int o = 1; o < 256; o <<= 1) {
                int t = (tid >= o) ? sh[tid - o] : 0;
                __syncthreads();
                sh[tid] += t;
                __syncthreads();
            }
            int incl = sh[tid];
            if (i < N) g_off[i] = incl - v;
            if (tid == 255) g_part[b] = incl;
            __syncthreads();
        }
        gbar(3, csr_n);
        if (ccta == 0) {
            int v = (tid < nblk) ? __ldcg(&g_part[tid]) : 0;
            sh[tid] = v;
            __syncthreads();
#pragma unroll
            for (int o = 1; o < 256; o <<= 1) {
                int t = (tid >= o) ? sh[tid - o] : 0;
                __syncthreads();
                sh[tid] += t;
                __syncthreads();
            }
            if (tid < nblk) g_part[tid] = sh[tid] - v;
        }
        gbar(4, csr_n);
        for (int b = ccta; b < nblk; b += (int)csr_n) {
            int boff = __ldcg(&g_part[b]);
            int i = b * 256 + tid;
            if (i < N) {
                int o = g_off[i] + boff;
                g_off[i] = o;
                g_cur[i] = o;
                g_dinv[i] = rsqrtf((float)__ldcg(&g_deg[i]));
            }
        }
        if (ccta == 0 && tid == 0) g_off[N] = E;
        gbar(5, csr_n);
        for (int e = ccta * 256 + tid; e < E; e += (int)csr_n * 256) {
            int p = atomicAdd(&g_cur[dst[e]], 1);
            g_csr[p] = src[e];
        }
    }

    // ---- join all CTAs ----
    gbar(6, (unsigned)ncta);

    const int gw0   = cta * 8 + (tid >> 5);
    const int gstep = ncta * 8;

    agg_phase<true>(g_h, b0, nullptr, N, gw0, gstep);          // layer 0
    gbar(7, (unsigned)ncta);
    gemm_phase<128, false>(g_ah, g_al, nullptr, g_wh + 32768, g_wl + 32768,
                           g_h, N, cta, ncta, smem);           // layer 1 GEMM
    gbar(8, (unsigned)ncta);
    agg_phase<true>(g_h, b1, nullptr, N, gw0, gstep);
    gbar(9, (unsigned)ncta);
    gemm_phase<128, false>(g_ah, g_al, nullptr, g_wh + 49152, g_wl + 49152,
                           g_h, N, cta, ncta, smem);           // layer 2 GEMM
    gbar(10, (unsigned)ncta);
    agg_phase<false>(g_h, b2, g_z, N, gw0, gstep);             // -> z fp16
    gbar(11, (unsigned)ncta);
    decode_phase(g_z, la, lb, logits, EL, gw0, gstep);
}

extern "C" void kernel_launch(void* const* d_in, const int* in_sizes, int n_in,
                              void* d_out, int out_size)
{
    const float* x   = (const float*)d_in[0];
    const int*   ei  = (const int*)d_in[1];
    const int*   eli = (const int*)d_in[2];
    const float* W0  = (const float*)d_in[3];
    const float* b0  = (const float*)d_in[4];
    const float* W1  = (const float*)d_in[5];
    const float* b1  = (const float*)d_in[6];
    const float* W2  = (const float*)d_in[7];
    const float* b2  = (const float*)d_in[8];
    float* logits = (float*)d_out;

    const int N  = in_sizes[0] / 256;   // 50000
    const int E  = in_sizes[1] / 2;     // 320000
    const int EL = in_sizes[2] / 2;     // 200000
    const int* src = ei;
    const int* dst = ei + E;
    const int* la  = eli;
    const int* lb  = eli + EL;

    const int SMEM = (2 * 128 * 264 + 4 * 128 * 24) * 2;  // 159744 (K=256 layout)

    static int ncta = 0;
    if (ncta == 0) {
        cudaDeviceGetAttribute(&ncta, cudaDevAttrMultiProcessorCount, 0);
        if (ncta > 256) ncta = 256;          // clamp (barrier slots sized for this)
        cudaFuncSetAttribute(mega_kernel,
                             cudaFuncAttributeMaxDynamicSharedMemorySize, SMEM);
    }

    mega_kernel<<<ncta, 256, SMEM>>>(x, src, dst, la, lb,
                                     W0, b0, W1, b1, W2, b2,
                                     logits, N, E, EL, ncta);
}

// round 15
// speedup vs baseline: 2.0729x; 2.0729x over previous
#include <cuda_runtime.h>
#include <cuda_bf16.h>
#include <cuda_fp16.h>
#include <math.h>
#include <stdint.h>

#define NND 50000
#define EMAX 320000
#define HDIM 128

// ---------------- scratch (device globals; allocation-free contract) --------
__device__ int            g_deg[NND];
__device__ float          g_dinv[NND];
__device__ __half         g_h[(size_t)NND * HDIM];     // fp16 message buffer
__device__ __half         g_z[(size_t)NND * HDIM];     // final z (fp16)
__device__ __nv_bfloat16  g_ah[(size_t)NND * HDIM];
__device__ __nv_bfloat16  g_al[(size_t)NND * HDIM];
// W0 at [0, 32768), W1 at [32768, 49152), W2 at [49152, 65536)
__device__ __nv_bfloat16  g_wh[65536];
__device__ __nv_bfloat16  g_wl[65536];
// CSR
__device__ int g_off[NND + 1];
__device__ int g_cur[NND];
__device__ int g_csr[EMAX];
__device__ int g_part[256];
// grid barrier counters (monotone across launches; generation counting)
__device__ unsigned g_barrier[8];

// ---------------- grid barrier (persistent kernel, generation counting) -----
__device__ __forceinline__ void gbar(int slot, unsigned count) {
    __threadfence();
    __syncthreads();
    if (threadIdx.x == 0) {
        unsigned old = atomicAdd(&g_barrier[slot], 1u);
        unsigned target = old - (old % count) + count;
        while (*(volatile unsigned*)&g_barrier[slot] < target) __nanosleep(64);
        __threadfence();
    }
    __syncthreads();
}

// ---------------- fused CSR build (ONE persistent kernel, side stream) ------
// phases: deg init -> atomic count -> block scans -> part scan -> add+dinv -> fill
__global__ __launch_bounds__(256, 2) void csr_persist_kernel(
    const int* __restrict__ src, const int* __restrict__ dst,
    int N, int E, int ncta)
{
    __shared__ int sh[256];
    const int cta = blockIdx.x, tid = threadIdx.x;
    const unsigned cnt = (unsigned)ncta;
    const int nblk = (N + 255) / 256;

    // phase 1: deg init (self-loop)
    for (int i = cta * 256 + tid; i < N; i += ncta * 256) g_deg[i] = 1;
    gbar(0, cnt);
    // phase 2: indegree count
    for (int e = cta * 256 + tid; e < E; e += ncta * 256)
        atomicAdd(&g_deg[dst[e]], 1);
    gbar(1, cnt);
    // phase 3: block-local exclusive scans
    for (int b = cta; b < nblk; b += ncta) {
        int i = b * 256 + tid;
        int v = (i < N) ? __ldcg(&g_deg[i]) - 1 : 0;
        sh[tid] = v;
        __syncthreads();
#pragma unroll
        for (int o = 1; o < 256; o <<= 1) {
            int t = (tid >= o) ? sh[tid - o] : 0;
            __syncthreads();
            sh[tid] += t;
            __syncthreads();
        }
        int incl = sh[tid];
        if (i < N) g_off[i] = incl - v;
        if (tid == 255) g_part[b] = incl;
        __syncthreads();
    }
    gbar(2, cnt);
    // phase 4: scan of block partials (CTA 0)
    if (cta == 0) {
        int v = (tid < nblk) ? __ldcg(&g_part[tid]) : 0;
        sh[tid] = v;
        __syncthreads();
#pragma unroll
        for (int o = 1; o < 256; o <<= 1) {
            int t = (tid >= o) ? sh[tid - o] : 0;
            __syncthreads();
            sh[tid] += t;
            __syncthreads();
        }
        if (tid < nblk) g_part[tid] = sh[tid] - v;
    }
    gbar(3, cnt);
    // phase 5: add block offsets, init cursors, dinv
    for (int b = cta; b < nblk; b += ncta) {
        int boff = __ldcg(&g_part[b]);
        int i = b * 256 + tid;
        if (i < N) {
            int o = g_off[i] + boff;
            g_off[i] = o;
            g_cur[i] = o;
            g_dinv[i] = rsqrtf((float)__ldcg(&g_deg[i]));
        }
    }
    if (cta == 0 && tid == 0) g_off[N] = E;
    gbar(4, cnt);
    // phase 6: CSR fill
    for (int e = cta * 256 + tid; e < E; e += ncta * 256) {
        int p = atomicAdd(&g_cur[dst[e]], 1);
        g_csr[p] = src[e];
    }
}

// ---------------- W split (main branch) --------------------------------------
__global__ void convw_kernel(const float* __restrict__ W0,
                             const float* __restrict__ W1,
                             const float* __restrict__ W2) {
    int j = blockIdx.x * blockDim.x + threadIdx.x;
    if (j >= 65536) return;
    const float* W; int K, jj = j;
    if (j < 32768)      { W = W0; K = 256; }
    else if (j < 49152) { W = W1; K = 128; jj -= 32768; }
    else                { W = W2; K = 128; jj -= 49152; }
    int nn = jj / K, k = jj % K;
    float v = W[k * 128 + nn];
    float h = __bfloat162float(__float2bfloat16(v));
    g_wh[j] = __float2bfloat16(h);
    g_wl[j] = __float2bfloat16(v - h);
}

// ---------------- bf16 split helpers ----------------
__device__ __forceinline__ void split_store4(float4 v, __nv_bfloat16* ah,
                                             __nv_bfloat16* al, size_t off) {
    float hx = __bfloat162float(__float2bfloat16(v.x));
    float hy = __bfloat162float(__float2bfloat16(v.y));
    float hz = __bfloat162float(__float2bfloat16(v.z));
    float hw = __bfloat162float(__float2bfloat16(v.w));
    __nv_bfloat162 h01 = __floats2bfloat162_rn(hx, hy);
    __nv_bfloat162 h23 = __floats2bfloat162_rn(hz, hw);
    __nv_bfloat162 l01 = __floats2bfloat162_rn(v.x - hx, v.y - hy);
    __nv_bfloat162 l23 = __floats2bfloat162_rn(v.z - hz, v.w - hw);
    uint2 hp, lp;
    hp.x = *(uint32_t*)&h01; hp.y = *(uint32_t*)&h23;
    lp.x = *(uint32_t*)&l01; lp.y = *(uint32_t*)&l23;
    *(uint2*)&ah[off] = hp;
    *(uint2*)&al[off] = lp;
}

// ---------------- HMMA GEMM: H(fp16) = A @ W^T  (bf16x3 split, raw) ----------
#define MMA16816(d, a, b) \
    asm volatile( \
        "mma.sync.aligned.m16n8k16.row.col.f32.bf16.bf16.f32 " \
        "{%0,%1,%2,%3}, {%4,%5,%6,%7}, {%8,%9}, {%0,%1,%2,%3};" \
        : "+f"((d)[0]), "+f"((d)[1]), "+f"((d)[2]), "+f"((d)[3]) \
        : "r"((a)[0]), "r"((a)[1]), "r"((a)[2]), "r"((a)[3]), \
          "r"((b)[0]), "r"((b)[1]))

// FUSE=true: A comes from fp32 Xf (split to hi/lo in registers during copy).
template <int K, bool FUSE, int MINBLK>
__global__ __launch_bounds__(256, MINBLK) void gemm_mma_kernel(
    const __nv_bfloat16* __restrict__ Ah, const __nv_bfloat16* __restrict__ Al,
    const float* __restrict__ Xf,
    const __nv_bfloat16* __restrict__ Wh, const __nv_bfloat16* __restrict__ Wl,
    __half* __restrict__ H, int M)
{
    extern __shared__ char smem[];
    const int PW = K + 8;   // W row pitch (bf16)
    const int PA = 24;      // A row pitch (bf16)

    __nv_bfloat16* sWh = (__nv_bfloat16*)smem;
    __nv_bfloat16* sWl = sWh + 128 * PW;
    __nv_bfloat16* sA  = sWl + 128 * PW;   // [stage][buf][128][PA]

    const int tid = threadIdx.x, lane = tid & 31, wid = tid >> 5;
    const int wm = wid & 3, wn = wid >> 2;     // warp tile: 32 rows x 64 cols
    const int m0 = blockIdx.x * 128;

    const int WCH = 128 * (K / 8);
    for (int i = tid; i < WCH; i += 256) {
        int n = i / (K / 8), c = i % (K / 8);
        *(uint4*)(sWh + n * PW + c * 8) = *(const uint4*)(Wh + n * K + c * 8);
        *(uint4*)(sWl + n * PW + c * 8) = *(const uint4*)(Wl + n * K + c * 8);
    }

    auto copyA = [&](int ks, int st) {
        if (FUSE) {
            int row = tid >> 1, half = tid & 1;
            int gr = m0 + row;
            float4 v0 = make_float4(0.f, 0.f, 0.f, 0.f), v1 = v0;
            if (gr < M) {
                const float4* p = (const float4*)(Xf + (size_t)gr * K + ks * 16 + half * 8);
                v0 = p[0]; v1 = p[1];
            }
            float f[8] = {v0.x, v0.y, v0.z, v0.w, v1.x, v1.y, v1.z, v1.w};
            uint32_t hi[4], lo[4];
#pragma unroll
            for (int j = 0; j < 4; j++) {
                float a = f[2 * j], b = f[2 * j + 1];
                float ha = __bfloat162float(__float2bfloat16(a));
                float hb = __bfloat162float(__float2bfloat16(b));
                __nv_bfloat162 hh = __floats2bfloat162_rn(ha, hb);
                __nv_bfloat162 ll = __floats2bfloat162_rn(a - ha, b - hb);
                hi[j] = *(uint32_t*)&hh;
                lo[j] = *(uint32_t*)&ll;
            }
            __nv_bfloat16* dh = sA + ((st * 2 + 0) * 128 + row) * PA + half * 8;
            __nv_bfloat16* dl = sA + ((st * 2 + 1) * 128 + row) * PA + half * 8;
            *(uint4*)dh = make_uint4(hi[0], hi[1], hi[2], hi[3]);
            *(uint4*)dl = make_uint4(lo[0], lo[1], lo[2], lo[3]);
        } else {
            int buf = tid >> 7, row = tid & 127;
            int gr = m0 + row;
            const __nv_bfloat16* src = buf ? Al : Ah;
            uint4 v0 = make_uint4(0u, 0u, 0u, 0u), v1 = v0;
            if (gr < M) {
                const uint4* p = (const uint4*)(src + (size_t)gr * K + ks * 16);
                v0 = p[0]; v1 = p[1];
            }
            __nv_bfloat16* d = sA + ((st * 2 + buf) * 128 + row) * PA;
            *(uint4*)d = v0; *(uint4*)(d + 8) = v1;
        }
    };

    float acc[2][8][4];
#pragma unroll
    for (int mt = 0; mt < 2; mt++)
#pragma unroll
        for (int nt = 0; nt < 8; nt++)
#pragma unroll
            for (int j = 0; j < 4; j++) acc[mt][nt][j] = 0.f;

    const int NS = K / 16;
    copyA(0, 0);
    __syncthreads();

    const int ar0 = wm * 32 + (lane >> 2);
    const int kk  = (lane & 3) * 2;
    const int nb  = wn * 64 + (lane >> 2);

    for (int ks = 0; ks < NS; ks++) {
        int st = ks & 1;
        if (ks + 1 < NS) copyA(ks + 1, st ^ 1);

        const __nv_bfloat16* Abh = sA + (st * 2 + 0) * 128 * PA;
        const __nv_bfloat16* Abl = sA + (st * 2 + 1) * 128 * PA;

        uint32_t ah[2][4], al[2][4];
#pragma unroll
        for (int mt = 0; mt < 2; mt++) {
            int r = ar0 + mt * 16;
            ah[mt][0] = *(const uint32_t*)(Abh + r * PA + kk);
            ah[mt][1] = *(const uint32_t*)(Abh + (r + 8) * PA + kk);
            ah[mt][2] = *(const uint32_t*)(Abh + r * PA + kk + 8);
            ah[mt][3] = *(const uint32_t*)(Abh + (r + 8) * PA + kk + 8);
            al[mt][0] = *(const uint32_t*)(Abl + r * PA + kk);
            al[mt][1] = *(const uint32_t*)(Abl + (r + 8) * PA + kk);
            al[mt][2] = *(const uint32_t*)(Abl + r * PA + kk + 8);
            al[mt][3] = *(const uint32_t*)(Abl + (r + 8) * PA + kk + 8);
        }
        uint32_t bh[8][2], bl[8][2];
        int kw = ks * 16 + kk;
#pragma unroll
        for (int nt = 0; nt < 8; nt++) {
            const __nv_bfloat16* ph = sWh + (nb + nt * 8) * PW + kw;
            const __nv_bfloat16* pl = sWl + (nb + nt * 8) * PW + kw;
            bh[nt][0] = *(const uint32_t*)ph;
            bh[nt][1] = *(const uint32_t*)(ph + 8);
            bl[nt][0] = *(const uint32_t*)pl;
            bl[nt][1] = *(const uint32_t*)(pl + 8);
        }
#pragma unroll
        for (int mt = 0; mt < 2; mt++)
#pragma unroll
            for (int nt = 0; nt < 8; nt++) {
                MMA16816(acc[mt][nt], ah[mt], bh[nt]);  // hi*hi
                MMA16816(acc[mt][nt], ah[mt], bl[nt]);  // hi*lo
                MMA16816(acc[mt][nt], al[mt], bh[nt]);  // lo*hi
            }
        __syncthreads();
    }

    // ---- epilogue: write raw H as fp16 ----
    const int cbase = wn * 64 + (lane & 3) * 2;
#pragma unroll
    for (int mt = 0; mt < 2; mt++) {
        int ra = m0 + wm * 32 + mt * 16 + (lane >> 2);
        int rb = ra + 8;
#pragma unroll
        for (int nt = 0; nt < 8; nt++) {
            int col = cbase + nt * 8;
            if (ra < M)
                *(__half2*)&H[(size_t)ra * HDIM + col] =
                    __floats2half2_rn(acc[mt][nt][0], acc[mt][nt][1]);
            if (rb < M)
                *(__half2*)&H[(size_t)rb * HDIM + col] =
                    __floats2half2_rn(acc[mt][nt][2], acc[mt][nt][3]);
        }
    }
}

// ---------------- fused aggregate + finalize (fp16 msgs, 4x pipelined) -------
__device__ __forceinline__ void acc_row(float4& acc, uint2 rv, float ds) {
    float2 v01 = __half22float2(*(__half2*)&rv.x);
    float2 v23 = __half22float2(*(__half2*)&rv.y);
    acc.x = fmaf(v01.x, ds, acc.x); acc.y = fmaf(v01.y, ds, acc.y);
    acc.z = fmaf(v23.x, ds, acc.z); acc.w = fmaf(v23.y, ds, acc.w);
}
template <bool BF16OUT>
__global__ __launch_bounds__(256) void agg_fin_kernel(
    const __half* __restrict__ H, const float* __restrict__ bias,
    __half* __restrict__ OUT, int N)
{
    int gw   = (blockIdx.x * blockDim.x + threadIdx.x) >> 5;
    int lane = threadIdx.x & 31;
    if (gw >= N) return;
    int s0 = g_off[gw], s1 = g_off[gw + 1];
    float di = g_dinv[gw];

    uint2 raw = *(const uint2*)&H[(size_t)gw * HDIM + lane * 4];   // self
    float2 p01 = __half22float2(*(__half2*)&raw.x);
    float2 p23 = __half22float2(*(__half2*)&raw.y);
    float4 acc = make_float4(p01.x * di, p01.y * di, p23.x * di, p23.y * di);

    int j = s0;
    for (; j + 4 <= s1; j += 4) {                  // 4x software pipeline
        int sa = g_csr[j],     sb = g_csr[j + 1];
        int sc = g_csr[j + 2], sd = g_csr[j + 3];
        float da = __ldg(&g_dinv[sa]), db = __ldg(&g_dinv[sb]);
        float dc = __ldg(&g_dinv[sc]), dd = __ldg(&g_dinv[sd]);
        uint2 ra = __ldg((const uint2*)&H[(size_t)sa * HDIM + lane * 4]);
        uint2 rb = __ldg((const uint2*)&H[(size_t)sb * HDIM + lane * 4]);
        uint2 rc = __ldg((const uint2*)&H[(size_t)sc * HDIM + lane * 4]);
        uint2 rd = __ldg((const uint2*)&H[(size_t)sd * HDIM + lane * 4]);
        acc_row(acc, ra, da); acc_row(acc, rb, db);
        acc_row(acc, rc, dc); acc_row(acc, rd, dd);
    }
    for (; j < s1; j++) {
        int s = g_csr[j];
        float ds = __ldg(&g_dinv[s]);
        uint2 rv = __ldg((const uint2*)&H[(size_t)s * HDIM + lane * 4]);
        acc_row(acc, rv, ds);
    }

    float4 bb = *(const float4*)&bias[lane * 4];
    acc.x = acc.x * di + bb.x; acc.y = acc.y * di + bb.y;
    acc.z = acc.z * di + bb.z; acc.w = acc.w * di + bb.w;
    if (BF16OUT) {
        acc.x = fmaxf(acc.x, 0.f); acc.y = fmaxf(acc.y, 0.f);
        acc.z = fmaxf(acc.z, 0.f); acc.w = fmaxf(acc.w, 0.f);
        split_store4(acc, g_ah, g_al, (size_t)gw * HDIM + lane * 4);
    } else {
        uint2 o;
        *(__half2*)&o.x = __floats2half2_rn(acc.x, acc.y);
        *(__half2*)&o.y = __floats2half2_rn(acc.z, acc.w);
        *(uint2*)&OUT[(size_t)gw * HDIM + lane * 4] = o;
    }
}

// ---------------- decode: logits[e] = dot(Z[a], Z[b]), fp16 z, 1 warp/edge ---
__global__ __launch_bounds__(256) void decode_kernel(
    const __half* __restrict__ Z, const int* __restrict__ ea,
    const int* __restrict__ eb, float* __restrict__ out, int EL)
{
    int gw   = (blockIdx.x * blockDim.x + threadIdx.x) >> 5;
    int lane = threadIdx.x & 31;
    if (gw >= EL) return;
    int i = ea[gw], j = eb[gw];
    uint2 ru = __ldg((const uint2*)&Z[(size_t)i * HDIM + lane * 4]);
    uint2 rv = __ldg((const uint2*)&Z[(size_t)j * HDIM + lane * 4]);
    float2 u01 = __half22float2(*(__half2*)&ru.x);
    float2 u23 = __half22float2(*(__half2*)&ru.y);
    float2 v01 = __half22float2(*(__half2*)&rv.x);
    float2 v23 = __half22float2(*(__half2*)&rv.y);
    float p = u01.x * v01.x + u01.y * v01.y + u23.x * v23.x + u23.y * v23.y;
#pragma unroll
    for (int o = 16; o; o >>= 1) p += __shfl_xor_sync(0xffffffffu, p, o);
    if (lane == 0) out[gw] = p;
}

extern "C" void kernel_launch(void* const* d_in, const int* in_sizes, int n_in,
                              void* d_out, int out_size)
{
    const float* x   = (const float*)d_in[0];
    const int*   ei  = (const int*)d_in[1];
    const int*   eli = (const int*)d_in[2];
    const float* W0  = (const float*)d_in[3];
    const float* b0  = (const float*)d_in[4];
    const float* W1  = (const float*)d_in[5];
    const float* b1  = (const float*)d_in[6];
    const float* W2  = (const float*)d_in[7];
    const float* b2  = (const float*)d_in[8];
    float* logits = (float*)d_out;

    const int N  = in_sizes[0] / 256;   // 50000
    const int E  = in_sizes[1] / 2;     // 320000
    const int EL = in_sizes[2] / 2;     // 200000
    const int* src = ei;
    const int* dst = ei + E;
    const int* la  = eli;
    const int* lb  = eli + EL;

    __half *p_h, *p_z;
    __nv_bfloat16 *p_ah, *p_al, *p_wh, *p_wl;
    cudaGetSymbolAddress((void**)&p_h,  g_h);
    cudaGetSymbolAddress((void**)&p_z,  g_z);
    cudaGetSymbolAddress((void**)&p_ah, g_ah);
    cudaGetSymbolAddress((void**)&p_al, g_al);
    cudaGetSymbolAddress((void**)&p_wh, g_wh);
    cudaGetSymbolAddress((void**)&p_wl, g_wl);

    const int SMEM256 = (2 * 128 * 264 + 4 * 128 * 24) * 2;  // 159744
    const int SMEM128 = (2 * 128 * 136 + 4 * 128 * 24) * 2;  //  94208

    // one-time host setup (attributes, stream/events, SM count)
    static cudaStream_t s_side = nullptr;
    static cudaEvent_t  s_ev0 = nullptr, s_ev1 = nullptr;
    static int ncta_side = 0;
    if (s_side == nullptr) {
        cudaStreamCreateWithFlags(&s_side, cudaStreamNonBlocking);
        cudaEventCreateWithFlags(&s_ev0, cudaEventDisableTiming);
        cudaEventCreateWithFlags(&s_ev1, cudaEventDisableTiming);
        int nsm = 0;
        cudaDeviceGetAttribute(&nsm, cudaDevAttrMultiProcessorCount, 0);
        ncta_side = nsm * 2;                 // 2 CTAs/SM: always co-resident
        cudaFuncSetAttribute((gemm_mma_kernel<256, true, 1>),
                             cudaFuncAttributeMaxDynamicSharedMemorySize, SMEM256);
        cudaFuncSetAttribute((gemm_mma_kernel<128, false, 2>),
                             cudaFuncAttributeMaxDynamicSharedMemorySize, SMEM128);
    }

    const int TB = 256;
    const int mtiles     = (N + 127) / 128;
    const int agg_blocks = (N + 7) / 8;

    // ---- fork: side branch = ONE persistent kernel building degrees+CSR+dinv
    cudaEventRecord(s_ev0, 0);
    cudaStreamWaitEvent(s_side, s_ev0, 0);
    csr_persist_kernel<<<ncta_side, TB, 0, s_side>>>(src, dst, N, E, ncta_side);
    cudaEventRecord(s_ev1, s_side);

    // ---- main branch: W split + layer-0 GEMM (no dinv dependency) ----
    convw_kernel<<<(65536 + TB - 1) / TB, TB>>>(W0, W1, W2);
    gemm_mma_kernel<256, true, 1><<<mtiles, TB, SMEM256>>>(
        nullptr, nullptr, x, p_wh, p_wl, p_h, N);

    // ---- join ----
    cudaStreamWaitEvent(0, s_ev1, 0);

    agg_fin_kernel<true><<<agg_blocks, TB>>>(p_h, b0, nullptr, N);

    // Layer 1: K=128
    gemm_mma_kernel<128, false, 2><<<mtiles, TB, SMEM128>>>(
        p_ah, p_al, nullptr, p_wh + 32768, p_wl + 32768, p_h, N);
    agg_fin_kernel<true><<<agg_blocks, TB>>>(p_h, b1, nullptr, N);

    // Layer 2: K=128, no relu, fp16 z out
    gemm_mma_kernel<128, false, 2><<<mtiles, TB, SMEM128>>>(
        p_ah, p_al, nullptr, p_wh + 49152, p_wl + 49152, p_h, N);
    agg_fin_kernel<false><<<agg_blocks, TB>>>(p_h, b2, p_z, N);

    // Decode
    decode_kernel<<<(EL + 7) / 8, TB>>>(p_z, la, lb, logits, EL);
}

// round 16
// speedup vs baseline: 2.1558x; 1.0400x over previous
#include <cuda_runtime.h>
#include <cuda_bf16.h>
#include <cuda_fp16.h>
#include <math.h>
#include <stdint.h>

#define NND 50000
#define EMAX 320000
#define HDIM 128

// ---------------- scratch (device globals; allocation-free contract) --------
__device__ int            g_deg[NND];
__device__ float          g_dinv[NND];
__device__ float          g_h[(size_t)NND * HDIM];     // fp32 message buffer
__device__ __half         g_z[(size_t)NND * HDIM];     // final z (fp16)
__device__ __nv_bfloat16  g_ah[(size_t)NND * HDIM];
__device__ __nv_bfloat16  g_al[(size_t)NND * HDIM];
// W0 at [0, 32768), W1 at [32768, 49152), W2 at [49152, 65536)
__device__ __nv_bfloat16  g_wh[65536];
__device__ __nv_bfloat16  g_wl[65536];
// CSR
__device__ int g_off[NND + 1];
__device__ int g_cur[NND];
__device__ int g_csr[EMAX];
__device__ int g_part[256];

// ---------------- W split (main branch) --------------------------------------
__global__ void convw_kernel(const float* __restrict__ W0,
                             const float* __restrict__ W1,
                             const float* __restrict__ W2) {
    int j = blockIdx.x * blockDim.x + threadIdx.x;
    if (j >= 65536) return;
    const float* W; int K, jj = j;
    if (j < 32768)      { W = W0; K = 256; }
    else if (j < 49152) { W = W1; K = 128; jj -= 32768; }
    else                { W = W2; K = 128; jj -= 49152; }
    int nn = jj / K, k = jj % K;
    float v = W[k * 128 + nn];
    float h = __bfloat162float(__float2bfloat16(v));
    g_wh[j] = __float2bfloat16(h);
    g_wl[j] = __float2bfloat16(v - h);
}

// ---------------- degree / CSR (side branch) ----------------------------------
__global__ void deg_init_kernel(int n) {
    int i = blockIdx.x * blockDim.x + threadIdx.x;
    if (i < n) g_deg[i] = 1;  // self-loop
}
__global__ void deg_count_kernel(const int* __restrict__ dst, int E) {
    for (int e = blockIdx.x * blockDim.x + threadIdx.x; e < E;
         e += gridDim.x * blockDim.x)
        atomicAdd(&g_deg[dst[e]], 1);
}
__global__ void scan_block_kernel(int n) {
    __shared__ int sh[256];
    int i = blockIdx.x * 256 + threadIdx.x;
    int v = (i < n) ? g_deg[i] - 1 : 0;
    sh[threadIdx.x] = v;
    __syncthreads();
#pragma unroll
    for (int o = 1; o < 256; o <<= 1) {
        int t = (threadIdx.x >= o) ? sh[threadIdx.x - o] : 0;
        __syncthreads();
        sh[threadIdx.x] += t;
        __syncthreads();
    }
    int incl = sh[threadIdx.x];
    if (i < n) g_off[i] = incl - v;                 // block-local exclusive
    if (threadIdx.x == 255) g_part[blockIdx.x] = incl;
}
// block offset: warp 0 reduces g_part[j < bid]; +dinv fused
__global__ void scan_add_kernel(int n, int E, int nb) {
    __shared__ int s_boff;
    int t = threadIdx.x, bid = blockIdx.x;
    if (t < 32) {
        int acc = 0;
        for (int j = t; j < bid; j += 32) acc += g_part[j];
#pragma unroll
        for (int o = 16; o; o >>= 1) acc += __shfl_xor_sync(0xffffffffu, acc, o);
        if (t == 0) s_boff = acc;
    }
    __syncthreads();
    int i = bid * 256 + t;
    if (i < n) {
        int o = g_off[i] + s_boff;
        g_off[i] = o;
        g_cur[i] = o;
        g_dinv[i] = rsqrtf((float)g_deg[i]);
    }
    if (i == 0) g_off[n] = E;
}
__global__ void csr_fill_kernel(const int* __restrict__ src,
                                const int* __restrict__ dst, int E) {
    for (int e = blockIdx.x * blockDim.x + threadIdx.x; e < E;
         e += gridDim.x * blockDim.x) {
        int p = atomicAdd(&g_cur[dst[e]], 1);
        g_csr[p] = src[e];
    }
}

// ---------------- bf16 split helpers ----------------
__device__ __forceinline__ void split_store4(float4 v, __nv_bfloat16* ah,
                                             __nv_bfloat16* al, size_t off) {
    float hx = __bfloat162float(__float2bfloat16(v.x));
    float hy = __bfloat162float(__float2bfloat16(v.y));
    float hz = __bfloat162float(__float2bfloat16(v.z));
    float hw = __bfloat162float(__float2bfloat16(v.w));
    __nv_bfloat162 h01 = __floats2bfloat162_rn(hx, hy);
    __nv_bfloat162 h23 = __floats2bfloat162_rn(hz, hw);
    __nv_bfloat162 l01 = __floats2bfloat162_rn(v.x - hx, v.y - hy);
    __nv_bfloat162 l23 = __floats2bfloat162_rn(v.z - hz, v.w - hw);
    uint2 hp, lp;
    hp.x = *(uint32_t*)&h01; hp.y = *(uint32_t*)&h23;
    lp.x = *(uint32_t*)&l01; lp.y = *(uint32_t*)&l23;
    *(uint2*)&ah[off] = hp;
    *(uint2*)&al[off] = lp;
}

// ---------------- HMMA GEMM: H(fp32) = A @ W^T  (bf16x3 split, raw) ----------
#define MMA16816(d, a, b) \
    asm volatile( \
        "mma.sync.aligned.m16n8k16.row.col.f32.bf16.bf16.f32 " \
        "{%0,%1,%2,%3}, {%4,%5,%6,%7}, {%8,%9}, {%0,%1,%2,%3};" \
        : "+f"((d)[0]), "+f"((d)[1]), "+f"((d)[2]), "+f"((d)[3]) \
        : "r"((a)[0]), "r"((a)[1]), "r"((a)[2]), "r"((a)[3]), \
          "r"((b)[0]), "r"((b)[1]))

// FUSE=true: A comes from fp32 Xf (split to hi/lo in registers during copy).
template <int K, bool FUSE, int MINBLK>
__global__ __launch_bounds__(256, MINBLK) void gemm_mma_kernel(
    const __nv_bfloat16* __restrict__ Ah, const __nv_bfloat16* __restrict__ Al,
    const float* __restrict__ Xf,
    const __nv_bfloat16* __restrict__ Wh, const __nv_bfloat16* __restrict__ Wl,
    float* __restrict__ H, int M)
{
    extern __shared__ char smem[];
    const int PW = K + 8;   // W row pitch (bf16)
    const int PA = 24;      // A row pitch (bf16)

    __nv_bfloat16* sWh = (__nv_bfloat16*)smem;
    __nv_bfloat16* sWl = sWh + 128 * PW;
    __nv_bfloat16* sA  = sWl + 128 * PW;   // [stage][buf][128][PA]

    const int tid = threadIdx.x, lane = tid & 31, wid = tid >> 5;
    const int wm = wid & 3, wn = wid >> 2;     // warp tile: 32 rows x 64 cols
    const int m0 = blockIdx.x * 128;

    const int WCH = 128 * (K / 8);
    for (int i = tid; i < WCH; i += 256) {
        int n = i / (K / 8), c = i % (K / 8);
        *(uint4*)(sWh + n * PW + c * 8) = *(const uint4*)(Wh + n * K + c * 8);
        *(uint4*)(sWl + n * PW + c * 8) = *(const uint4*)(Wl + n * K + c * 8);
    }

    auto copyA = [&](int ks, int st) {
        if (FUSE) {
            int row = tid >> 1, half = tid & 1;
            int gr = m0 + row;
            float4 v0 = make_float4(0.f, 0.f, 0.f, 0.f), v1 = v0;
            if (gr < M) {
                const float4* p = (const float4*)(Xf + (size_t)gr * K + ks * 16 + half * 8);
                v0 = p[0]; v1 = p[1];
            }
            float f[8] = {v0.x, v0.y, v0.z, v0.w, v1.x, v1.y, v1.z, v1.w};
            uint32_t hi[4], lo[4];
#pragma unroll
            for (int j = 0; j < 4; j++) {
                float a = f[2 * j], b = f[2 * j + 1];
                float ha = __bfloat162float(__float2bfloat16(a));
                float hb = __bfloat162float(__float2bfloat16(b));
                __nv_bfloat162 hh = __floats2bfloat162_rn(ha, hb);
                __nv_bfloat162 ll = __floats2bfloat162_rn(a - ha, b - hb);
                hi[j] = *(uint32_t*)&hh;
                lo[j] = *(uint32_t*)&ll;
            }
            __nv_bfloat16* dh = sA + ((st * 2 + 0) * 128 + row) * PA + half * 8;
            __nv_bfloat16* dl = sA + ((st * 2 + 1) * 128 + row) * PA + half * 8;
            *(uint4*)dh = make_uint4(hi[0], hi[1], hi[2], hi[3]);
            *(uint4*)dl = make_uint4(lo[0], lo[1], lo[2], lo[3]);
        } else {
            int buf = tid >> 7, row = tid & 127;
            int gr = m0 + row;
            const __nv_bfloat16* src = buf ? Al : Ah;
            uint4 v0 = make_uint4(0u, 0u, 0u, 0u), v1 = v0;
            if (gr < M) {
                const uint4* p = (const uint4*)(src + (size_t)gr * K + ks * 16);
                v0 = p[0]; v1 = p[1];
            }
            __nv_bfloat16* d = sA + ((st * 2 + buf) * 128 + row) * PA;
            *(uint4*)d = v0; *(uint4*)(d + 8) = v1;
        }
    };

    float acc[2][8][4];
#pragma unroll
    for (int mt = 0; mt < 2; mt++)
#pragma unroll
        for (int nt = 0; nt < 8; nt++)
#pragma unroll
            for (int j = 0; j < 4; j++) acc[mt][nt][j] = 0.f;

    const int NS = K / 16;
    copyA(0, 0);
    __syncthreads();

    const int ar0 = wm * 32 + (lane >> 2);
    const int kk  = (lane & 3) * 2;
    const int nb  = wn * 64 + (lane >> 2);

    for (int ks = 0; ks < NS; ks++) {
        int st = ks & 1;
        if (ks + 1 < NS) copyA(ks + 1, st ^ 1);

        const __nv_bfloat16* Abh = sA + (st * 2 + 0) * 128 * PA;
        const __nv_bfloat16* Abl = sA + (st * 2 + 1) * 128 * PA;

        uint32_t ah[2][4], al[2][4];
#pragma unroll
        for (int mt = 0; mt < 2; mt++) {
            int r = ar0 + mt * 16;
            ah[mt][0] = *(const uint32_t*)(Abh + r * PA + kk);
            ah[mt][1] = *(const uint32_t*)(Abh + (r + 8) * PA + kk);
            ah[mt][2] = *(const uint32_t*)(Abh + r * PA + kk + 8);
            ah[mt][3] = *(const uint32_t*)(Abh + (r + 8) * PA + kk + 8);
            al[mt][0] = *(const uint32_t*)(Abl + r * PA + kk);
            al[mt][1] = *(const uint32_t*)(Abl + (r + 8) * PA + kk);
            al[mt][2] = *(const uint32_t*)(Abl + r * PA + kk + 8);
            al[mt][3] = *(const uint32_t*)(Abl + (r + 8) * PA + kk + 8);
        }
        uint32_t bh[8][2], bl[8][2];
        int kw = ks * 16 + kk;
#pragma unroll
        for (int nt = 0; nt < 8; nt++) {
            const __nv_bfloat16* ph = sWh + (nb + nt * 8) * PW + kw;
            const __nv_bfloat16* pl = sWl + (nb + nt * 8) * PW + kw;
            bh[nt][0] = *(const uint32_t*)ph;
            bh[nt][1] = *(const uint32_t*)(ph + 8);
            bl[nt][0] = *(const uint32_t*)pl;
            bl[nt][1] = *(const uint32_t*)(pl + 8);
        }
#pragma unroll
        for (int mt = 0; mt < 2; mt++)
#pragma unroll
            for (int nt = 0; nt < 8; nt++) {
                MMA16816(acc[mt][nt], ah[mt], bh[nt]);  // hi*hi
                MMA16816(acc[mt][nt], ah[mt], bl[nt]);  // hi*lo
                MMA16816(acc[mt][nt], al[mt], bh[nt]);  // lo*hi
            }
        __syncthreads();
    }

    // ---- epilogue: write raw H (fp32) ----
    const int cbase = wn * 64 + (lane & 3) * 2;
#pragma unroll
    for (int mt = 0; mt < 2; mt++) {
        int ra = m0 + wm * 32 + mt * 16 + (lane >> 2);
        int rb = ra + 8;
#pragma unroll
        for (int nt = 0; nt < 8; nt++) {
            int col = cbase + nt * 8;
            if (ra < M)
                *(float2*)&H[(unsigned)ra * HDIM + col] =
                    make_float2(acc[mt][nt][0], acc[mt][nt][1]);
            if (rb < M)
                *(float2*)&H[(unsigned)rb * HDIM + col] =
                    make_float2(acc[mt][nt][2], acc[mt][nt][3]);
        }
    }
}

// ---------------- fused aggregate + finalize (fp32 msgs, 4x pipelined) -------
// inner = dinv[d]*H[d] + sum_s dinv[s]*H[s];  out = inner*dinv[d] + b; [relu]
__device__ __forceinline__ void fma4(float4& acc, float4 v, float ds) {
    acc.x = fmaf(v.x, ds, acc.x); acc.y = fmaf(v.y, ds, acc.y);
    acc.z = fmaf(v.z, ds, acc.z); acc.w = fmaf(v.w, ds, acc.w);
}
template <bool BF16OUT>
__global__ __launch_bounds__(256) void agg_fin_kernel(
    const float* __restrict__ H, const float* __restrict__ bias,
    __half* __restrict__ OUT, int N)
{
    int gw   = (blockIdx.x * blockDim.x + threadIdx.x) >> 5;
    int lane = threadIdx.x & 31;
    if (gw >= N) return;
    int s0 = g_off[gw], s1 = g_off[gw + 1];
    float di = g_dinv[gw];
    const float4* H4 = (const float4*)H;   // 32 float4 per row

    float4 acc = H4[((unsigned)gw << 5) + lane];   // self
    acc.x *= di; acc.y *= di; acc.z *= di; acc.w *= di;

    int j = s0;
    for (; j + 4 <= s1; j += 4) {                  // 4x software pipeline
        unsigned sa = (unsigned)g_csr[j],     sb = (unsigned)g_csr[j + 1];
        unsigned sc = (unsigned)g_csr[j + 2], sd = (unsigned)g_csr[j + 3];
        float da = __ldg(&g_dinv[sa]), db = __ldg(&g_dinv[sb]);
        float dc = __ldg(&g_dinv[sc]), dd = __ldg(&g_dinv[sd]);
        float4 ra = __ldg(H4 + (sa << 5) + lane);
        float4 rb = __ldg(H4 + (sb << 5) + lane);
        float4 rc = __ldg(H4 + (sc << 5) + lane);
        float4 rd = __ldg(H4 + (sd << 5) + lane);
        fma4(acc, ra, da); fma4(acc, rb, db);
        fma4(acc, rc, dc); fma4(acc, rd, dd);
    }
    for (; j < s1; j++) {
        unsigned s = (unsigned)g_csr[j];
        float ds = __ldg(&g_dinv[s]);
        float4 rv = __ldg(H4 + (s << 5) + lane);
        fma4(acc, rv, ds);
    }

    float4 bb = *(const float4*)&bias[lane * 4];
    acc.x = acc.x * di + bb.x; acc.y = acc.y * di + bb.y;
    acc.z = acc.z * di + bb.z; acc.w = acc.w * di + bb.w;
    if (BF16OUT) {
        acc.x = fmaxf(acc.x, 0.f); acc.y = fmaxf(acc.y, 0.f);
        acc.z = fmaxf(acc.z, 0.f); acc.w = fmaxf(acc.w, 0.f);
        split_store4(acc, g_ah, g_al, ((size_t)gw << 7) + lane * 4);
    } else {
        uint2 o;
        *(__half2*)&o.x = __floats2half2_rn(acc.x, acc.y);
        *(__half2*)&o.y = __floats2half2_rn(acc.z, acc.w);
        *(uint2*)&OUT[((unsigned)gw << 7) + lane * 4] = o;
    }
}

// ---------------- decode: logits[e] = dot(Z[a], Z[b]), fp16 z, 1 warp/edge ---
__global__ __launch_bounds__(256) void decode_kernel(
    const __half* __restrict__ Z, const int* __restrict__ ea,
    const int* __restrict__ eb, float* __restrict__ out, int EL)
{
    int gw   = (blockIdx.x * blockDim.x + threadIdx.x) >> 5;
    int lane = threadIdx.x & 31;
    if (gw >= EL) return;
    unsigned i = (unsigned)ea[gw], j = (unsigned)eb[gw];
    const uint2* Z2 = (const uint2*)Z;      // 32 uint2 per row
    uint2 ru = __ldg(Z2 + (i << 5) + lane);
    uint2 rv = __ldg(Z2 + (j << 5) + lane);
    float2 u01 = __half22float2(*(__half2*)&ru.x);
    float2 u23 = __half22float2(*(__half2*)&ru.y);
    float2 v01 = __half22float2(*(__half2*)&rv.x);
    float2 v23 = __half22float2(*(__half2*)&rv.y);
    float p = u01.x * v01.x + u01.y * v01.y + u23.x * v23.x + u23.y * v23.y;
#pragma unroll
    for (int o = 16; o; o >>= 1) p += __shfl_xor_sync(0xffffffffu, p, o);
    if (lane == 0) out[gw] = p;
}

extern "C" void kernel_launch(void* const* d_in, const int* in_sizes, int n_in,
                              void* d_out, int out_size)
{
    const float* x   = (const float*)d_in[0];
    const int*   ei  = (const int*)d_in[1];
    const int*   eli = (const int*)d_in[2];
    const float* W0  = (const float*)d_in[3];
    const float* b0  = (const float*)d_in[4];
    const float* W1  = (const float*)d_in[5];
    const float* b1  = (const float*)d_in[6];
    const float* W2  = (const float*)d_in[7];
    const float* b2  = (const float*)d_in[8];
    float* logits = (float*)d_out;

    const int N  = in_sizes[0] / 256;   // 50000
    const int E  = in_sizes[1] / 2;     // 320000
    const int EL = in_sizes[2] / 2;     // 200000
    const int* src = ei;
    const int* dst = ei + E;
    const int* la  = eli;
    const int* lb  = eli + EL;

    float *p_h;
    __half *p_z;
    __nv_bfloat16 *p_ah, *p_al, *p_wh, *p_wl;
    cudaGetSymbolAddress((void**)&p_h,  g_h);
    cudaGetSymbolAddress((void**)&p_z,  g_z);
    cudaGetSymbolAddress((void**)&p_ah, g_ah);
    cudaGetSymbolAddress((void**)&p_al, g_al);
    cudaGetSymbolAddress((void**)&p_wh, g_wh);
    cudaGetSymbolAddress((void**)&p_wl, g_wl);

    const int SMEM256 = (2 * 128 * 264 + 4 * 128 * 24) * 2;  // 159744
    const int SMEM128 = (2 * 128 * 136 + 4 * 128 * 24) * 2;  //  94208

    static cudaStream_t s_side = nullptr;
    static cudaEvent_t  s_ev0 = nullptr, s_ev1 = nullptr;
    if (s_side == nullptr) {
        cudaStreamCreateWithFlags(&s_side, cudaStreamNonBlocking);
        cudaEventCreateWithFlags(&s_ev0, cudaEventDisableTiming);
        cudaEventCreateWithFlags(&s_ev1, cudaEventDisableTiming);
        cudaFuncSetAttribute((gemm_mma_kernel<256, true, 1>),
                             cudaFuncAttributeMaxDynamicSharedMemorySize, SMEM256);
        cudaFuncSetAttribute((gemm_mma_kernel<128, false, 2>),
                             cudaFuncAttributeMaxDynamicSharedMemorySize, SMEM128);
    }

    const int TB = 256;
    const int nscan      = (N + 255) / 256;
    const int mtiles     = (N + 127) / 128;
    const int agg_blocks = (N + 7) / 8;

    // ---- fork: side branch builds degrees + CSR + dinv ----
    cudaEventRecord(s_ev0, 0);
    cudaStreamWaitEvent(s_side, s_ev0, 0);
    deg_init_kernel<<<(N + TB - 1) / TB, TB, 0, s_side>>>(N);
    deg_count_kernel<<<512, TB, 0, s_side>>>(dst, E);
    scan_block_kernel<<<nscan, 256, 0, s_side>>>(N);
    scan_add_kernel<<<nscan, 256, 0, s_side>>>(N, E, nscan);
    csr_fill_kernel<<<512, TB, 0, s_side>>>(src, dst, E);
    cudaEventRecord(s_ev1, s_side);

    // ---- main branch: W split + layer-0 GEMM (no dinv dependency) ----
    convw_kernel<<<(65536 + TB - 1) / TB, TB>>>(W0, W1, W2);
    gemm_mma_kernel<256, true, 1><<<mtiles, TB, SMEM256>>>(
        nullptr, nullptr, x, p_wh, p_wl, p_h, N);

    // ---- join ----
    cudaStreamWaitEvent(0, s_ev1, 0);

    agg_fin_kernel<true><<<agg_blocks, TB>>>(p_h, b0, nullptr, N);

    // Layer 1: K=128
    gemm_mma_kernel<128, false, 2><<<mtiles, TB, SMEM128>>>(
        p_ah, p_al, nullptr, p_wh + 32768, p_wl + 32768, p_h, N);
    agg_fin_kernel<true><<<agg_blocks, TB>>>(p_h, b1, nullptr, N);

    // Layer 2: K=128, no relu, fp16 z out
    gemm_mma_kernel<128, false, 2><<<mtiles, TB, SMEM128>>>(
        p_ah, p_al, nullptr, p_wh + 49152, p_wl + 49152, p_h, N);
    agg_fin_kernel<false><<<agg_blocks, TB>>>(p_h, b2, p_z, N);

    // Decode
    decode_kernel<<<(EL + 7) / 8, TB>>>(p_z, la, lb, logits, EL);
}

// round 17
// speedup vs baseline: 2.9780x; 1.3814x over previous
#include <cuda_runtime.h>
#include <cuda_fp16.h>
#include <math.h>
#include <stdint.h>

#define NND 50000
#define EMAX 320000
#define HDIM 128

// ---------------- scratch (device globals; allocation-free contract) --------
__device__ int     g_deg[NND];
__device__ float   g_dinv[NND];
__device__ float   g_h[(size_t)NND * HDIM];     // fp32 message buffer
__device__ __half  g_z[(size_t)NND * HDIM];     // final z (fp16)
__device__ __half  g_a16[(size_t)NND * HDIM];   // fp16 activations (GEMM A)
// W0 at [0, 32768), W1 at [32768, 49152), W2 at [49152, 65536) — fp16, [N,K]
__device__ __half  g_w[65536];
// CSR
__device__ int g_off[NND + 1];
__device__ int g_cur[NND];
__device__ int g_csr[EMAX];
__device__ int g_part[256];

// ---------------- W convert (main branch) ------------------------------------
__global__ void convw_kernel(const float* __restrict__ W0,
                             const float* __restrict__ W1,
                             const float* __restrict__ W2) {
    int j = blockIdx.x * blockDim.x + threadIdx.x;
    if (j >= 65536) return;
    const float* W; int K, jj = j;
    if (j < 32768)      { W = W0; K = 256; }
    else if (j < 49152) { W = W1; K = 128; jj -= 32768; }
    else                { W = W2; K = 128; jj -= 49152; }
    int nn = jj / K, k = jj % K;
    g_w[j] = __float2half(W[k * 128 + nn]);
}

// ---------------- degree / CSR (side branch) ----------------------------------
__global__ void deg_init_kernel(int n) {
    int i = blockIdx.x * blockDim.x + threadIdx.x;
    if (i < n) g_deg[i] = 1;  // self-loop
}
__global__ void deg_count_kernel(const int* __restrict__ dst, int E) {
    for (int e = blockIdx.x * blockDim.x + threadIdx.x; e < E;
         e += gridDim.x * blockDim.x)
        atomicAdd(&g_deg[dst[e]], 1);
}
__global__ void scan_block_kernel(int n) {
    __shared__ int sh[256];
    int i = blockIdx.x * 256 + threadIdx.x;
    int v = (i < n) ? g_deg[i] - 1 : 0;
    sh[threadIdx.x] = v;
    __syncthreads();
#pragma unroll
    for (int o = 1; o < 256; o <<= 1) {
        int t = (threadIdx.x >= o) ? sh[threadIdx.x - o] : 0;
        __syncthreads();
        sh[threadIdx.x] += t;
        __syncthreads();
    }
    int incl = sh[threadIdx.x];
    if (i < n) g_off[i] = incl - v;                 // block-local exclusive
    if (threadIdx.x == 255) g_part[blockIdx.x] = incl;
}
__global__ void scan_add_kernel(int n, int E, int nb) {
    __shared__ int s_boff;
    int t = threadIdx.x, bid = blockIdx.x;
    if (t < 32) {
        int acc = 0;
        for (int j = t; j < bid; j += 32) acc += g_part[j];
#pragma unroll
        for (int o = 16; o; o >>= 1) acc += __shfl_xor_sync(0xffffffffu, acc, o);
        if (t == 0) s_boff = acc;
    }
    __syncthreads();
    int i = bid * 256 + t;
    if (i < n) {
        int o = g_off[i] + s_boff;
        g_off[i] = o;
        g_cur[i] = o;
        g_dinv[i] = rsqrtf((float)g_deg[i]);
    }
    if (i == 0) g_off[n] = E;
}
__global__ void csr_fill_kernel(const int* __restrict__ src,
                                const int* __restrict__ dst, int E) {
    for (int e = blockIdx.x * blockDim.x + threadIdx.x; e < E;
         e += gridDim.x * blockDim.x) {
        int p = atomicAdd(&g_cur[dst[e]], 1);
        g_csr[p] = src[e];
    }
}

// ---------------- HMMA GEMM: H(fp32) = A @ W^T  (single fp16 MMA) ------------
#define MMA16816F16(d, a, b) \
    asm volatile( \
        "mma.sync.aligned.m16n8k16.row.col.f32.f16.f16.f32 " \
        "{%0,%1,%2,%3}, {%4,%5,%6,%7}, {%8,%9}, {%0,%1,%2,%3};" \
        : "+f"((d)[0]), "+f"((d)[1]), "+f"((d)[2]), "+f"((d)[3]) \
        : "r"((a)[0]), "r"((a)[1]), "r"((a)[2]), "r"((a)[3]), \
          "r"((b)[0]), "r"((b)[1]))

// FUSE=true: A comes from fp32 Xf (converted to fp16 in registers during copy).
template <int K, bool FUSE, int MINBLK>
__global__ __launch_bounds__(256, MINBLK) void gemm_mma_kernel(
    const __half* __restrict__ Af, const float* __restrict__ Xf,
    const __half* __restrict__ W16, float* __restrict__ H, int M)
{
    extern __shared__ char smem[];
    const int PW = K + 8;   // W row pitch (fp16)
    const int PA = 24;      // A row pitch (fp16)

    __half* sW = (__half*)smem;            // [128][PW]
    __half* sA = sW + 128 * PW;            // [stage][128][PA]

    const int tid = threadIdx.x, lane = tid & 31, wid = tid >> 5;
    const int wm = wid & 3, wn = wid >> 2;     // warp tile: 32 rows x 64 cols
    const int m0 = blockIdx.x * 128;

    const int WCH = 128 * (K / 8);
    for (int i = tid; i < WCH; i += 256) {
        int n = i / (K / 8), c = i % (K / 8);
        *(uint4*)(sW + n * PW + c * 8) = *(const uint4*)(W16 + n * K + c * 8);
    }

    // A k-slice copy: 128 rows x 16 fp16 (2 threads/row, 8 halves each)
    auto copyA = [&](int ks, int st) {
        int row = tid >> 1, half = tid & 1;
        int gr = m0 + row;
        uint4 out = make_uint4(0u, 0u, 0u, 0u);
        if (FUSE) {
            if (gr < M) {
                const float4* p = (const float4*)(Xf + (size_t)gr * K + ks * 16 + half * 8);
                float4 v0 = p[0], v1 = p[1];
                __half2 h0 = __floats2half2_rn(v0.x, v0.y);
                __half2 h1 = __floats2half2_rn(v0.z, v0.w);
                __half2 h2 = __floats2half2_rn(v1.x, v1.y);
                __half2 h3 = __floats2half2_rn(v1.z, v1.w);
                out = make_uint4(*(uint32_t*)&h0, *(uint32_t*)&h1,
                                 *(uint32_t*)&h2, *(uint32_t*)&h3);
            }
        } else {
            if (gr < M)
                out = *(const uint4*)(Af + (size_t)gr * K + ks * 16 + half * 8);
        }
        *(uint4*)(sA + (st * 128 + row) * PA + half * 8) = out;
    };

    float acc[2][8][4];
#pragma unroll
    for (int mt = 0; mt < 2; mt++)
#pragma unroll
        for (int nt = 0; nt < 8; nt++)
#pragma unroll
            for (int j = 0; j < 4; j++) acc[mt][nt][j] = 0.f;

    const int NS = K / 16;
    copyA(0, 0);
    __syncthreads();

    const int ar0 = wm * 32 + (lane >> 2);
    const int kk  = (lane & 3) * 2;
    const int nb  = wn * 64 + (lane >> 2);

    for (int ks = 0; ks < NS; ks++) {
        int st = ks & 1;
        if (ks + 1 < NS) copyA(ks + 1, st ^ 1);

        const __half* Ab = sA + st * 128 * PA;

        uint32_t a[2][4];
#pragma unroll
        for (int mt = 0; mt < 2; mt++) {
            int r = ar0 + mt * 16;
            a[mt][0] = *(const uint32_t*)(Ab + r * PA + kk);
            a[mt][1] = *(const uint32_t*)(Ab + (r + 8) * PA + kk);
            a[mt][2] = *(const uint32_t*)(Ab + r * PA + kk + 8);
            a[mt][3] = *(const uint32_t*)(Ab + (r + 8) * PA + kk + 8);
        }
        uint32_t b[8][2];
        int kw = ks * 16 + kk;
#pragma unroll
        for (int nt = 0; nt < 8; nt++) {
            const __half* ph = sW + (nb + nt * 8) * PW + kw;
            b[nt][0] = *(const uint32_t*)ph;
            b[nt][1] = *(const uint32_t*)(ph + 8);
        }
#pragma unroll
        for (int mt = 0; mt < 2; mt++)
#pragma unroll
            for (int nt = 0; nt < 8; nt++)
                MMA16816F16(acc[mt][nt], a[mt], b[nt]);
        __syncthreads();
    }

    // ---- epilogue: write raw H (fp32) ----
    const int cbase = wn * 64 + (lane & 3) * 2;
#pragma unroll
    for (int mt = 0; mt < 2; mt++) {
        int ra = m0 + wm * 32 + mt * 16 + (lane >> 2);
        int rb = ra + 8;
#pragma unroll
        for (int nt = 0; nt < 8; nt++) {
            int col = cbase + nt * 8;
            if (ra < M)
                *(float2*)&H[(unsigned)ra * HDIM + col] =
                    make_float2(acc[mt][nt][0], acc[mt][nt][1]);
            if (rb < M)
                *(float2*)&H[(unsigned)rb * HDIM + col] =
                    make_float2(acc[mt][nt][2], acc[mt][nt][3]);
        }
    }
}

// ---------------- fused aggregate + finalize (fp32 msgs, 4x pipelined) -------
// inner = dinv[d]*H[d] + sum_s dinv[s]*H[s];  out = inner*dinv[d] + b; [relu]
__device__ __forceinline__ void fma4(float4& acc, float4 v, float ds) {
    acc.x = fmaf(v.x, ds, acc.x); acc.y = fmaf(v.y, ds, acc.y);
    acc.z = fmaf(v.z, ds, acc.z); acc.w = fmaf(v.w, ds, acc.w);
}
// RELU=true: relu then fp16 -> g_a16. else: fp16 -> OUT (z).
template <bool RELU>
__global__ __launch_bounds__(256) void agg_fin_kernel(
    const float* __restrict__ H, const float* __restrict__ bias,
    __half* __restrict__ OUT, int N)
{
    int gw   = (blockIdx.x * blockDim.x + threadIdx.x) >> 5;
    int lane = threadIdx.x & 31;
    if (gw >= N) return;
    int s0 = g_off[gw], s1 = g_off[gw + 1];
    float di = g_dinv[gw];
    const float4* H4 = (const float4*)H;   // 32 float4 per row

    float4 acc = H4[((unsigned)gw << 5) + lane];   // self
    acc.x *= di; acc.y *= di; acc.z *= di; acc.w *= di;

    int j = s0;
    for (; j + 4 <= s1; j += 4) {                  // 4x software pipeline
        unsigned sa = (unsigned)g_csr[j],     sb = (unsigned)g_csr[j + 1];
        unsigned sc = (unsigned)g_csr[j + 2], sd = (unsigned)g_csr[j + 3];
        float da = __ldg(&g_dinv[sa]), db = __ldg(&g_dinv[sb]);
        float dc = __ldg(&g_dinv[sc]), dd = __ldg(&g_dinv[sd]);
        float4 ra = __ldg(H4 + (sa << 5) + lane);
        float4 rb = __ldg(H4 + (sb << 5) + lane);
        float4 rc = __ldg(H4 + (sc << 5) + lane);
        float4 rd = __ldg(H4 + (sd << 5) + lane);
        fma4(acc, ra, da); fma4(acc, rb, db);
        fma4(acc, rc, dc); fma4(acc, rd, dd);
    }
    for (; j < s1; j++) {
        unsigned s = (unsigned)g_csr[j];
        float ds = __ldg(&g_dinv[s]);
        float4 rv = __ldg(H4 + (s << 5) + lane);
        fma4(acc, rv, ds);
    }

    float4 bb = *(const float4*)&bias[lane * 4];
    acc.x = acc.x * di + bb.x; acc.y = acc.y * di + bb.y;
    acc.z = acc.z * di + bb.z; acc.w = acc.w * di + bb.w;
    if (RELU) {
        acc.x = fmaxf(acc.x, 0.f); acc.y = fmaxf(acc.y, 0.f);
        acc.z = fmaxf(acc.z, 0.f); acc.w = fmaxf(acc.w, 0.f);
    }
    uint2 o;
    *(__half2*)&o.x = __floats2half2_rn(acc.x, acc.y);
    *(__half2*)&o.y = __floats2half2_rn(acc.z, acc.w);
    *(uint2*)&OUT[((unsigned)gw << 7) + lane * 4] = o;
}

// ---------------- decode: logits[e] = dot(Z[a], Z[b]), fp16 z, 1 warp/edge ---
__global__ __launch_bounds__(256) void decode_kernel(
    const __half* __restrict__ Z, const int* __restrict__ ea,
    const int* __restrict__ eb, float* __restrict__ out, int EL)
{
    int gw   = (blockIdx.x * blockDim.x + threadIdx.x) >> 5;
    int lane = threadIdx.x & 31;
    if (gw >= EL) return;
    unsigned i = (unsigned)ea[gw], j = (unsigned)eb[gw];
    const uint2* Z2 = (const uint2*)Z;      // 32 uint2 per row
    uint2 ru = __ldg(Z2 + (i << 5) + lane);
    uint2 rv = __ldg(Z2 + (j << 5) + lane);
    float2 u01 = __half22float2(*(__half2*)&ru.x);
    float2 u23 = __half22float2(*(__half2*)&ru.y);
    float2 v01 = __half22float2(*(__half2*)&rv.x);
    float2 v23 = __half22float2(*(__half2*)&rv.y);
    float p = u01.x * v01.x + u01.y * v01.y + u23.x * v23.x + u23.y * v23.y;
#pragma unroll
    for (int o = 16; o; o >>= 1) p += __shfl_xor_sync(0xffffffffu, p, o);
    if (lane == 0) out[gw] = p;
}

extern "C" void kernel_launch(void* const* d_in, const int* in_sizes, int n_in,
                              void* d_out, int out_size)
{
    const float* x   = (const float*)d_in[0];
    const int*   ei  = (const int*)d_in[1];
    const int*   eli = (const int*)d_in[2];
    const float* W0  = (const float*)d_in[3];
    const float* b0  = (const float*)d_in[4];
    const float* W1  = (const float*)d_in[5];
    const float* b1  = (const float*)d_in[6];
    const float* W2  = (const float*)d_in[7];
    const float* b2  = (const float*)d_in[8];
    float* logits = (float*)d_out;

    const int N  = in_sizes[0] / 256;   // 50000
    const int E  = in_sizes[1] / 2;     // 320000
    const int EL = in_sizes[2] / 2;     // 200000
    const int* src = ei;
    const int* dst = ei + E;
    const int* la  = eli;
    const int* lb  = eli + EL;

    float *p_h;
    __half *p_z, *p_a16, *p_w;
    cudaGetSymbolAddress((void**)&p_h,   g_h);
    cudaGetSymbolAddress((void**)&p_z,   g_z);
    cudaGetSymbolAddress((void**)&p_a16, g_a16);
    cudaGetSymbolAddress((void**)&p_w,   g_w);

    // smem: W 128*(K+8)*2 + A 2*128*24*2
    const int SMEM256 = 128 * 264 * 2 + 2 * 128 * 24 * 2;  // 79872
    const int SMEM128 = 128 * 136 * 2 + 2 * 128 * 24 * 2;  // 47104

    static cudaStream_t s_side = nullptr;
    static cudaEvent_t  s_ev0 = nullptr, s_ev1 = nullptr;
    if (s_side == nullptr) {
        cudaStreamCreateWithFlags(&s_side, cudaStreamNonBlocking);
        cudaEventCreateWithFlags(&s_ev0, cudaEventDisableTiming);
        cudaEventCreateWithFlags(&s_ev1, cudaEventDisableTiming);
        cudaFuncSetAttribute((gemm_mma_kernel<256, true, 2>),
                             cudaFuncAttributeMaxDynamicSharedMemorySize, SMEM256);
        cudaFuncSetAttribute((gemm_mma_kernel<128, false, 2>),
                             cudaFuncAttributeMaxDynamicSharedMemorySize, SMEM128);
    }

    const int TB = 256;
    const int nscan      = (N + 255) / 256;
    const int mtiles     = (N + 127) / 128;
    const int agg_blocks = (N + 7) / 8;

    // ---- fork: side branch builds degrees + CSR + dinv ----
    cudaEventRecord(s_ev0, 0);
    cudaStreamWaitEvent(s_side, s_ev0, 0);
    deg_init_kernel<<<(N + TB - 1) / TB, TB, 0, s_side>>>(N);
    deg_count_kernel<<<512, TB, 0, s_side>>>(dst, E);
    scan_block_kernel<<<nscan, 256, 0, s_side>>>(N);
    scan_add_kernel<<<nscan, 256, 0, s_side>>>(N, E, nscan);
    csr_fill_kernel<<<512, TB, 0, s_side>>>(src, dst, E);
    cudaEventRecord(s_ev1, s_side);

    // ---- main branch: W convert + layer-0 GEMM (no dinv dependency) ----
    convw_kernel<<<(65536 + TB - 1) / TB, TB>>>(W0, W1, W2);
    gemm_mma_kernel<256, true, 2><<<mtiles, TB, SMEM256>>>(
        nullptr, x, p_w, p_h, N);

    // ---- join ----
    cudaStreamWaitEvent(0, s_ev1, 0);

    agg_fin_kernel<true><<<agg_blocks, TB>>>(p_h, b0, p_a16, N);

    // Layer 1: K=128
    gemm_mma_kernel<128, false, 2><<<mtiles, TB, SMEM128>>>(
        p_a16, nullptr, p_w + 32768, p_h, N);
    agg_fin_kernel<true><<<agg_blocks, TB>>>(p_h, b1, p_a16, N);

    // Layer 2: K=128, no relu, fp16 z out
    gemm_mma_kernel<128, false, 2><<<mtiles, TB, SMEM128>>>(
        p_a16, nullptr, p_w + 49152, p_h, N);
    agg_fin_kernel<false><<<agg_blocks, TB>>>(p_h, b2, p_z, N);

    // Decode
    decode_kernel<<<(EL + 7) / 8, TB>>>(p_z, la, lb, logits, EL);
}